// round 8
// baseline (speedup 1.0000x reference)
#include <cuda_runtime.h>
#include <cuda_bf16.h>
#include <cstdint>

#define B_ 8
#define P_ 64
#define S_ 256
#define D_ 256

// ---------------- device scratch (zero-init at load; reset each run) ----------------
__device__ float g_partials[P_ * 32 * 5];
__device__ float g_scale[P_];
__device__ float g_bias[P_];
__device__ int   g_cnt[P_];
__device__ int   g_cnt2[P_];
__device__ int   g_flag[P_];

__device__ __forceinline__ uint32_t smem_to_u32(const void* p) {
    uint32_t a;
    asm("{ .reg .u64 t; cvta.to.shared.u64 t, %1; cvt.u32.u64 %0, t; }" : "=r"(a) : "l"(p));
    return a;
}

#define LDSM4(d0, d1, d2, d3, a) \
    asm volatile("ldmatrix.sync.aligned.m8n8.x4.shared.b16 {%0,%1,%2,%3}, [%4];" \
                 : "=r"(d0), "=r"(d1), "=r"(d2), "=r"(d3) : "r"(a))

#define HMMA(c, a0, a1, a2, a3, b0, b1) \
    asm volatile("mma.sync.aligned.m16n8k16.row.col.f32.bf16.bf16.f32 " \
                 "{%0,%1,%2,%3}, {%4,%5,%6,%7}, {%8,%9}, {%0,%1,%2,%3};" \
                 : "+f"((c)[0]), "+f"((c)[1]), "+f"((c)[2]), "+f"((c)[3]) \
                 : "r"(a0), "r"(a1), "r"(a2), "r"(a3), "r"(b0), "r"(b1))

#define CP_ASYNC16(dst, src) \
    asm volatile("cp.async.cg.shared.global [%0], [%1], 16;" :: "r"(dst), "l"(src))
#define CP_COMMIT() asm volatile("cp.async.commit_group;" ::: "memory")
#define CP_WAIT0()  asm volatile("cp.async.wait_group 0;" ::: "memory")

// ---------------- smem layout (bytes) ----------------
constexpr int STGB   = 144;                   // staging row: 32 fp32 =128B +16 pad
constexpr int ROWB   = 80;                    // bf16 row: 32 bf16 = 64B +16 pad
constexpr int OFF_STG = 0;                    // 256*144 = 36864
constexpr int OFF_BH  = 36864;                // 256*80 = 20480
constexpr int OFF_BL  = 57344;                // 20480
constexpr int SMEM_BYTES = 77824;             // 76KB -> 2 CTAs/SM
// epilogue overlay (everything above dead after last MMA):
constexpr int OFF_XSE  = 0;                   // 64*256*4 = 65536
constexpr int OFF_REDP = 65536;               // 64*17*4 = 4352
constexpr int OFF_RS   = OFF_REDP + 4352;     // 256
constexpr int OFF_S2   = OFF_RS + 256;        // 256
constexpr int OFF_RED  = OFF_S2 + 256;        // 256
constexpr int OFF_W8   = OFF_RED + 256;       // 32
constexpr int OFF_BC   = OFF_W8 + 32;         // 8   (total 70696 <= 77824)

// =====================================================================
// CTA = (b, p, q): rows [q*64, q*64+64), all 256 t-cols. 256 thr, 2 CTA/SM.
// =====================================================================
__global__ void __launch_bounds__(256, 2)
da_fused_kernel(const float* __restrict__ x, const float* __restrict__ w,
                const float* __restrict__ gamma, const float* __restrict__ beta,
                float* __restrict__ out)
{
    extern __shared__ __align__(16) char sm[];
    const uint32_t smb = smem_to_u32(sm);
    const int tid = threadIdx.x, wid = tid >> 5, lane = tid & 31;
    const int bx = blockIdx.x;                 // 0..31 = b*4 + q
    const int b = bx >> 2, q = bx & 3;
    const int p = blockIdx.y;
    const int m0 = q * 64;
    const float* xbp = x + (size_t)(b * P_ + p) * (S_ * D_);

    const int warp_m = wid >> 2;   // 0..1 : 32 m-rows
    const int warp_n = wid & 3;    // 0..3 : 64 n-cols

    // accumulators: 2 m-frags x 8 n-frags x 4 = 64 regs
    float acc[2][8][4];
    #pragma unroll
    for (int mi = 0; mi < 2; ++mi)
        #pragma unroll
        for (int nf = 0; nf < 8; ++nf)
            #pragma unroll
            for (int qq = 0; qq < 4; ++qq) acc[mi][nf][qq] = 0.f;

    // ldmatrix per-lane addressing
    const uint32_t lrow = lane & 15;
    const uint32_t lcol = (lane >> 4) * 16;
    uint32_t aaddr[2], baddr[4];
    #pragma unroll
    for (int mi = 0; mi < 2; ++mi)
        aaddr[mi] = smb + OFF_BH + (uint32_t)(m0 + warp_m * 32 + mi * 16 + lrow) * ROWB + lcol;
    #pragma unroll
    for (int nj = 0; nj < 4; ++nj)
        baddr[nj] = smb + OFF_BH + (uint32_t)(warp_n * 64 + nj * 16 + lrow) * ROWB + lcol;

    // copy/convert mapping: thread -> (16B column, row group)
    const int c8  = tid & 7;       // 16B col within 128B chunk row
    const int rb8 = tid >> 3;      // 0..31, rows rb8 + 32*j

    // ---- prologue: stream chunk 0 into staging ----
    {
        const float* xc = xbp + c8 * 4;
        #pragma unroll
        for (int j = 0; j < 8; ++j) {
            int row = rb8 + 32 * j;
            CP_ASYNC16(smb + OFF_STG + (uint32_t)row * STGB + (uint32_t)c8 * 16,
                       xc + (size_t)row * D_);
        }
        CP_COMMIT();
        CP_WAIT0();
    }
    __syncthreads();

    // ================= pipelined k-chunk loop (8 chunks of K=32) =================
    for (int kc = 0; kc < 8; ++kc) {
        // ---- convert staging (fp32) -> hi/lo bf16 buffers ----
        #pragma unroll
        for (int j = 0; j < 8; ++j) {
            int row = rb8 + 32 * j;
            float4 v = *reinterpret_cast<const float4*>(sm + OFF_STG + (size_t)row * STGB + c8 * 16);
            __nv_bfloat162 h01 = __floats2bfloat162_rn(v.x, v.y);
            __nv_bfloat162 h23 = __floats2bfloat162_rn(v.z, v.w);
            __nv_bfloat162 l01 = __floats2bfloat162_rn(v.x - __low2float(h01),
                                                       v.y - __high2float(h01));
            __nv_bfloat162 l23 = __floats2bfloat162_rn(v.z - __low2float(h23),
                                                       v.w - __high2float(h23));
            uint32_t off = (uint32_t)row * ROWB + (uint32_t)c8 * 8;
            *reinterpret_cast<uint2*>(sm + OFF_BH + off) =
                make_uint2(*reinterpret_cast<uint32_t*>(&h01), *reinterpret_cast<uint32_t*>(&h23));
            *reinterpret_cast<uint2*>(sm + OFF_BL + off) =
                make_uint2(*reinterpret_cast<uint32_t*>(&l01), *reinterpret_cast<uint32_t*>(&l23));
        }
        __syncthreads();   // staging consumed, bf16 buffers ready

        // ---- issue next chunk's async copies (latency hidden by MMA below) ----
        if (kc < 7) {
            const float* xn = xbp + (kc + 1) * 32 + c8 * 4;
            #pragma unroll
            for (int j = 0; j < 8; ++j) {
                int row = rb8 + 32 * j;
                CP_ASYNC16(smb + OFF_STG + (uint32_t)row * STGB + (uint32_t)c8 * 16,
                           xn + (size_t)row * D_);
            }
            CP_COMMIT();
        }

        // ---- MMA on bf16 buffers (2 K16-steps) ----
        #pragma unroll
        for (int ks = 0; ks < 2; ++ks) {
            const uint32_t ko = (uint32_t)ks * 32;
            uint32_t ah[2][4], al[2][4];
            #pragma unroll
            for (int mi = 0; mi < 2; ++mi) {
                LDSM4(ah[mi][0], ah[mi][1], ah[mi][2], ah[mi][3], aaddr[mi] + ko);
                LDSM4(al[mi][0], al[mi][1], al[mi][2], al[mi][3], aaddr[mi] + ko + 20480u);
            }
            #pragma unroll
            for (int nj = 0; nj < 4; ++nj) {
                uint32_t bh[4], bl[4];
                LDSM4(bh[0], bh[1], bh[2], bh[3], baddr[nj] + ko);
                LDSM4(bl[0], bl[1], bl[2], bl[3], baddr[nj] + ko + 20480u);
                #pragma unroll
                for (int nk = 0; nk < 2; ++nk) {
                    const int nf = nj * 2 + nk;
                    #pragma unroll
                    for (int mi = 0; mi < 2; ++mi) {
                        HMMA(acc[mi][nf], ah[mi][0], ah[mi][1], ah[mi][2], ah[mi][3],
                             bh[nk], bh[2 + nk]);                          // hi*hi
                        HMMA(acc[mi][nf], al[mi][0], al[mi][1], al[mi][2], al[mi][3],
                             bh[nk], bh[2 + nk]);                          // lo*hi
                        HMMA(acc[mi][nf], ah[mi][0], ah[mi][1], ah[mi][2], ah[mi][3],
                             bl[nk], bl[2 + nk]);                          // hi*lo
                    }
                }
            }
        }

        if (kc < 7) CP_WAIT0();
        __syncthreads();   // MMA readers done; staging refilled
    }

    // ================= stream this CTA's x rows into overlay via cp.async =================
    {
        const int c64 = tid & 63, rb4 = tid >> 6;
        const float* xr = xbp + (size_t)m0 * 256 + c64 * 4;
        #pragma unroll
        for (int j = 0; j < 16; ++j) {
            int row = rb4 + 4 * j;
            CP_ASYNC16(smb + OFF_XSE + (uint32_t)row * 1024 + (uint32_t)c64 * 16,
                       xr + (size_t)row * 256);
        }
        CP_COMMIT();
    }

    // ================= fold W into per-row partials (overlaps x streaming) =================
    float* redp = reinterpret_cast<float*>(sm + OFF_REDP);
    const float* wp = w + ((size_t)p << 16);
    #pragma unroll
    for (int mi = 0; mi < 2; ++mi)
        #pragma unroll
        for (int half = 0; half < 2; ++half) {
            int rl = warp_m * 32 + mi * 16 + (lane >> 2) + half * 8;   // 0..63 local
            const float* wr = wp + (size_t)(m0 + rl) * 256 + warp_n * 64 + (lane & 3) * 2;
            float part = 0.f;
            #pragma unroll
            for (int nf = 0; nf < 8; ++nf) {
                float2 wv = __ldg(reinterpret_cast<const float2*>(wr + nf * 8));
                part = fmaf(acc[mi][nf][half * 2 + 0], wv.x, part);
                part = fmaf(acc[mi][nf][half * 2 + 1], wv.y, part);
            }
            redp[rl * 17 + warp_n * 4 + (lane & 3)] = part;
        }
    CP_WAIT0();
    __syncthreads();

    // ================= row sums from smem x =================
    float* xs   = reinterpret_cast<float*>(sm + OFF_XSE);
    float* rssm = reinterpret_cast<float*>(sm + OFF_RS);
    float* s2sm = reinterpret_cast<float*>(sm + OFF_S2);
    #pragma unroll
    for (int j = 0; j < 8; ++j) {
        int r = wid * 8 + j;                       // 0..63 local
        float4 v0 = *reinterpret_cast<const float4*>(xs + r * 256 + lane * 4);
        float4 v1 = *reinterpret_cast<const float4*>(xs + r * 256 + 128 + lane * 4);
        float rsv = v0.x + v0.y + v0.z + v0.w + v1.x + v1.y + v1.z + v1.w;
        float s2v = v0.x * v0.x + v0.y * v0.y + v0.z * v0.z + v0.w * v0.w
                  + v1.x * v1.x + v1.y * v1.y + v1.z * v1.z + v1.w * v1.w;
        #pragma unroll
        for (int o = 16; o; o >>= 1) {
            rsv += __shfl_xor_sync(0xffffffffu, rsv, o);
            s2v += __shfl_xor_sync(0xffffffffu, s2v, o);
        }
        if (lane == 0) { rssm[r] = rsv; s2sm[r] = s2v; }
    }
    __syncthreads();

    // ================= finalize red + BN partials =================
    float* redsm = reinterpret_cast<float*>(sm + OFF_RED);
    float vals[5] = {0.f, 0.f, 0.f, 0.f, 0.f};
    if (tid < 64) {
        float rsum = 0.f;
        #pragma unroll
        for (int l = 0; l < 16; ++l) rsum += redp[tid * 17 + l];
        float red = rsum * 0.0625f;    // 1/sqrt(256)
        redsm[tid] = red;
        float xr = rssm[tid], x2 = s2sm[tid];
        vals[0] = xr; vals[1] = x2; vals[2] = red; vals[3] = red * red; vals[4] = red * xr;
    }
    float* w8 = reinterpret_cast<float*>(sm + OFF_W8);
    float out5[5];
    #pragma unroll
    for (int qq = 0; qq < 5; ++qq) {
        float v = vals[qq];
        #pragma unroll
        for (int o = 16; o; o >>= 1) v += __shfl_xor_sync(0xffffffffu, v, o);
        if (lane == 0) w8[wid] = v;
        __syncthreads();
        if (tid == 0) {
            float r = 0.f;
            for (int t = 0; t < 8; ++t) r += w8[t];
            out5[qq] = r;
        }
        __syncthreads();
    }

    // ================= cross-CTA BN handshake (32 CTAs per channel) =================
    float* bc = reinterpret_cast<float*>(sm + OFF_BC);
    if (tid == 0) {
        int slot = (p * 32 + bx) * 5;
        #pragma unroll
        for (int qq = 0; qq < 5; ++qq) g_partials[slot + qq] = out5[qq];
        __threadfence();
        int o = atomicAdd(&g_cnt[p], 1);
        if (o == 31) {
            __threadfence();
            float sx = 0.f, sx2 = 0.f, sr = 0.f, sr2 = 0.f, cr = 0.f;
            for (int c = 0; c < 32; ++c) {
                const float* qp = g_partials + (p * 32 + c) * 5;
                sx += qp[0]; sx2 += qp[1]; sr += qp[2]; sr2 += qp[3]; cr += qp[4];
            }
            const float N = (float)(B_ * S_ * D_);
            float sumy  = sx + (float)D_ * sr;
            float sumy2 = sx2 + 2.f * cr + (float)D_ * sr2;
            float mean = sumy / N;
            float var  = sumy2 / N - mean * mean;
            float sc = __ldg(gamma + p) * rsqrtf(var + 1e-5f);
            g_scale[p] = sc;
            g_bias[p]  = __ldg(beta + p) - mean * sc;
            __threadfence();
            atomicExch(&g_flag[p], 1);
        }
        volatile int* fl = (volatile int*)&g_flag[p];
        while (*fl == 0) __nanosleep(64);
        __threadfence();
        bc[0] = g_scale[p];
        bc[1] = g_bias[p];
        int o2 = atomicAdd(&g_cnt2[p], 1);
        if (o2 == 31) {        // all consumers done: reset for next graph replay
            g_flag[p] = 0; g_cnt[p] = 0; g_cnt2[p] = 0;
        }
    }
    __syncthreads();
    const float sc = bc[0], bi = bc[1];

    // ================= output: out = (x + red) * sc + bi =================
    float* ob = out + ((size_t)(b * P_ + p) << 16) + (size_t)m0 * 256;
    #pragma unroll
    for (int j = 0; j < 8; ++j) {
        int r = wid * 8 + j;
        float red = redsm[r];
        #pragma unroll
        for (int it = 0; it < 2; ++it) {
            float4 v = *reinterpret_cast<const float4*>(xs + r * 256 + it * 128 + lane * 4);
            v.x = fmaf(v.x + red, sc, bi);
            v.y = fmaf(v.y + red, sc, bi);
            v.z = fmaf(v.z + red, sc, bi);
            v.w = fmaf(v.w + red, sc, bi);
            *reinterpret_cast<float4*>(ob + (size_t)r * 256 + it * 128 + lane * 4) = v;
        }
    }
}

// =====================================================================
extern "C" void kernel_launch(void* const* d_in, const int* in_sizes, int n_in,
                              void* d_out, int out_size)
{
    const float* x     = (const float*)d_in[0];
    const float* w     = (const float*)d_in[1];
    const float* gamma = (const float*)d_in[2];
    const float* beta  = (const float*)d_in[3];
    float* out = (float*)d_out;

    cudaFuncSetAttribute(da_fused_kernel,
                         cudaFuncAttributeMaxDynamicSharedMemorySize, SMEM_BYTES);

    dim3 grid(32, P_);   // blockIdx.x = b*4+q (channel CTAs contiguous), blockIdx.y = p
    da_fused_kernel<<<grid, 256, SMEM_BYTES>>>(x, w, gamma, beta, out);
}